// round 15
// baseline (speedup 1.0000x reference)
#include <cuda_runtime.h>

#define B_ 8192
#define T_ 128
#define DT_ 0.01f
#define WARPS 4
#define THREADS 128
#define ROWS_PER_BLOCK 16
#define NBLK (B_ / ROWS_PER_BLOCK)

// shared memory layout (float offsets)
// W1s rows: 0..17 dynamic (e6, ed6, xi6); 18 = beta (xE); 19 = gamma (xnu); 20 = alpha
#define OFF_W1   0        // [21][512]
#define OFF_WEN2 10752    // [256]
#define OFF_WD2T 11008    // [6][256] (transposed Wd2)
#define SMEM_FLOATS 12544
#define SMEM_BYTES (SMEM_FLOATS * 4)

typedef unsigned long long u64;

__device__ __forceinline__ u64 ffma2(u64 a, u64 b, u64 c) {
    u64 d; asm("fma.rn.f32x2 %0, %1, %2, %3;" : "=l"(d) : "l"(a), "l"(b), "l"(c));
    return d;
}
__device__ __forceinline__ u64 dup2(float x) {
    u64 d; asm("mov.b64 %0, {%1, %1};" : "=l"(d) : "f"(x));
    return d;
}
__device__ __forceinline__ float2 unpk(u64 a) {
    float2 r; asm("mov.b64 {%0, %1}, %2;" : "=f"(r.x), "=f"(r.y) : "l"(a));
    return r;
}
__device__ __forceinline__ u64 pk2(float x, float y) {
    u64 d; asm("mov.b64 %0, {%1, %2};" : "=l"(d) : "f"(x), "f"(y));
    return d;
}
__device__ __forceinline__ u64 relu2(u64 a) {
    float2 v = unpk(a);
    return pk2(fmaxf(v.x, 0.f), fmaxf(v.y, 0.f));
}

__global__ void __launch_bounds__(THREADS, 3) visco_kernel(
    const float* __restrict__ e_,   const float* __restrict__ ed_,
    const float* __restrict__ E_,   const float* __restrict__ nu_,
    const float* __restrict__ We,   const float* __restrict__ be,
    const float* __restrict__ Wn,   const float* __restrict__ bn,
    const float* __restrict__ Wen1, const float* __restrict__ ben1,
    const float* __restrict__ Wen2, const float* __restrict__ ben2,
    const float* __restrict__ Wd1,  const float* __restrict__ bd1,
    const float* __restrict__ Wd2,  const float* __restrict__ bd2,
    float* __restrict__ out)
{
    extern __shared__ float sm[];
    float* W1s   = sm + OFF_W1;
    float* Wen2s = sm + OFF_WEN2;
    float* Wd2t  = sm + OFF_WD2T;

    const int tid  = threadIdx.x;
    const int lane = tid & 31;
    const int warp = tid >> 5;

    // ---- cooperative smem fill: dynamic W1 rows 0..17 + layer-2 weights ----
    for (int i = tid; i < 18 * 512; i += THREADS) {
        int k = i >> 9, h = i & 511;
        W1s[i] = (h < 256) ? Wen1[k * 256 + h] : Wd1[k * 256 + (h - 256)];
    }
    for (int i = tid; i < 256; i += THREADS) Wen2s[i] = Wen2[i];
    for (int i = tid; i < 6 * 256; i += THREADS) {
        int j = i >> 8, h = i & 255;
        Wd2t[i] = Wd2[h * 6 + j];   // transpose -> conflict-free float4 reads
    }

    // ---- rows 18..20: beta = We@W1mf, gamma = Wn@W1mf, alpha = bias fold ----
    // mf = [E*We+be, nu*Wn+bn]  =>  c[h] = alpha[h] + E*beta[h] + nu*gamma[h]
    {
        const int h0 = 4 * tid;
        const float* bsrc = (h0 < 256) ? (ben1 + h0) : (bd1 + h0 - 256);
        const float* Wb   = (h0 < 256) ? (Wen1 + 18 * 256 + h0)
                                       : (Wd1  + 18 * 256 + h0 - 256);
        float al[4], bt[4], gm[4];
        #pragma unroll
        for (int el = 0; el < 4; el++) { al[el] = bsrc[el]; bt[el] = 0.f; gm[el] = 0.f; }
        for (int i = 0; i < 16; i++) {
            float4 wa = *(const float4*)(Wb + i * 256);          // W1 row 18+i (E-encoder)
            float4 wb = *(const float4*)(Wb + (16 + i) * 256);   // W1 row 34+i (nu-encoder)
            float wev = We[i], bev = be[i], wnv = Wn[i], bnv = bn[i];
            bt[0] = fmaf(wev, wa.x, bt[0]); bt[1] = fmaf(wev, wa.y, bt[1]);
            bt[2] = fmaf(wev, wa.z, bt[2]); bt[3] = fmaf(wev, wa.w, bt[3]);
            gm[0] = fmaf(wnv, wb.x, gm[0]); gm[1] = fmaf(wnv, wb.y, gm[1]);
            gm[2] = fmaf(wnv, wb.z, gm[2]); gm[3] = fmaf(wnv, wb.w, gm[3]);
            al[0] = fmaf(bev, wa.x, al[0]); al[1] = fmaf(bev, wa.y, al[1]);
            al[2] = fmaf(bev, wa.z, al[2]); al[3] = fmaf(bev, wa.w, al[3]);
            al[0] = fmaf(bnv, wb.x, al[0]); al[1] = fmaf(bnv, wb.y, al[1]);
            al[2] = fmaf(bnv, wb.z, al[2]); al[3] = fmaf(bnv, wb.w, al[3]);
        }
        *(float4*)(W1s + 18 * 512 + h0) = make_float4(bt[0], bt[1], bt[2], bt[3]);
        *(float4*)(W1s + 19 * 512 + h0) = make_float4(gm[0], gm[1], gm[2], gm[3]);
        *(float4*)(W1s + 20 * 512 + h0) = make_float4(al[0], al[1], al[2], al[3]);
    }

    const int gw   = blockIdx.x * WARPS + warp;
    const int row0 = gw * 4;

    // per-row E/nu as scalar floats (dup2 at use, short live ranges)
    float Ef[4], nuf[4];
    #pragma unroll
    for (int r = 0; r < 4; r++) { Ef[r] = E_[row0 + r]; nuf[r] = nu_[row0 + r]; }

    // ---- distributed state: lane i = r*8+j owns output slot (r, j) ----
    const int jown = lane & 7;
    const int rown = lane >> 3;
    const float bd2v  = (jown < 6) ? bd2[jown] : 0.f;
    const float ben2r = ben2[0];
    float xi_val = 0.f;

    float* xi_ptr = out + B_ * T_ + ((row0 + rown) * T_) * 6 + jown;   // + t*6
    float* s_ptr  = out + (row0 + rown) * T_;                          // + t

    // lane -> (rowpair, input-dim) mapping for the per-step e/edot gather
    const int l2  = lane & 15;
    const bool ldp = (l2 < 12);
    const float* lsrc = (l2 < 6) ? e_ : ed_;
    const int d_l = (l2 < 6) ? l2 : (l2 - 6);
    const int rA = row0 + ((lane < 16) ? 0 : 1);
    const int rB = row0 + ((lane < 16) ? 2 : 3);
    const int base0 = rA * T_ * 6 + d_l;
    const int base1 = rB * T_ * 6 + d_l;

    const float* W1w   = W1s + 4 * lane;            // + k*512 + 128*q
    const float* wen2w = Wen2s + 4 * lane;          // + 128*q
    const float* wd2w  = Wd2t + 4 * lane;           // + j*256 + 128*q

    __syncthreads();

    u64 u2[4][4][2];   // [row][q][pair] — persists across the split step

    // FRONT(ldv0, ldv1): fused init (alpha + E*beta + nu*gamma) + k=0..11
    #define FRONT(LD0, LD1)                                                   \
    {                                                                         \
        u64 EdT[4], nudT[4];                                                  \
        _Pragma("unroll")                                                     \
        for (int r = 0; r < 4; r++) { EdT[r] = dup2(Ef[r]); nudT[r] = dup2(nuf[r]); } \
        _Pragma("unroll")                                                     \
        for (int q = 0; q < 4; q++) {                                         \
            ulonglong2 a  = *(const ulonglong2*)(W1w + 20 * 512 + 128 * q);   \
            ulonglong2 wg = *(const ulonglong2*)(W1w + 19 * 512 + 128 * q);   \
            ulonglong2 wb = *(const ulonglong2*)(W1w + 18 * 512 + 128 * q);   \
            _Pragma("unroll")                                                 \
            for (int r = 0; r < 4; r++) {                                     \
                u2[r][q][0] = ffma2(nudT[r], wg.x, a.x);                      \
                u2[r][q][1] = ffma2(nudT[r], wg.y, a.y);                      \
                u2[r][q][0] = ffma2(EdT[r], wb.x, u2[r][q][0]);               \
                u2[r][q][1] = ffma2(EdT[r], wb.y, u2[r][q][1]);               \
            }                                                                 \
        }                                                                     \
        _Pragma("unroll")                                                     \
        for (int k = 0; k < 12; k++) {                                        \
            u64 xd[4];                                                        \
            xd[0] = dup2(__shfl_sync(0xffffffffu, (LD0), k));                 \
            xd[1] = dup2(__shfl_sync(0xffffffffu, (LD0), 16 + k));            \
            xd[2] = dup2(__shfl_sync(0xffffffffu, (LD1), k));                 \
            xd[3] = dup2(__shfl_sync(0xffffffffu, (LD1), 16 + k));            \
            _Pragma("unroll")                                                 \
            for (int q = 0; q < 4; q++) {                                     \
                ulonglong2 w = *(const ulonglong2*)(W1w + k * 512 + 128 * q); \
                _Pragma("unroll")                                             \
                for (int r = 0; r < 4; r++) {                                 \
                    u2[r][q][0] = ffma2(xd[r], w.x, u2[r][q][0]);             \
                    u2[r][q][1] = ffma2(xd[r], w.y, u2[r][q][1]);             \
                }                                                             \
            }                                                                 \
        }                                                                     \
    }

    // prologue: front for t=0
    {
        float c0 = 0.f, c1 = 0.f;
        if (ldp) { c0 = lsrc[base0]; c1 = lsrc[base1]; }
        FRONT(c0, c1)
    }

    for (int t = 0; t < T_; t++) {
        // prefetch e/ed(t+1) — consumed by front(t+1) at iteration end
        float nxt0 = 0.f, nxt1 = 0.f;
        {
            int tn = (t + 1 < T_) ? (t + 1) : (T_ - 1);
            if (ldp) { nxt0 = lsrc[base0 + tn * 6]; nxt1 = lsrc[base1 + tn * 6]; }
        }

        // ---- back half: xi inputs k=12..17 (xi_val is step-t state) ----
        #pragma unroll
        for (int k = 12; k < 18; k++) {
            const int js = k - 12;
            u64 xd[4];
            xd[0] = dup2(__shfl_sync(0xffffffffu, xi_val, 0 * 8 + js));
            xd[1] = dup2(__shfl_sync(0xffffffffu, xi_val, 1 * 8 + js));
            xd[2] = dup2(__shfl_sync(0xffffffffu, xi_val, 2 * 8 + js));
            xd[3] = dup2(__shfl_sync(0xffffffffu, xi_val, 3 * 8 + js));
            #pragma unroll
            for (int q = 0; q < 4; q++) {
                ulonglong2 w = *(const ulonglong2*)(W1w + k * 512 + 128 * q);
                #pragma unroll
                for (int r = 0; r < 4; r++) {
                    u2[r][q][0] = ffma2(xd[r], w.x, u2[r][q][0]);
                    u2[r][q][1] = ffma2(xd[r], w.y, u2[r][q][1]);
                }
            }
        }

        // relu
        #pragma unroll
        for (int q = 0; q < 4; q++)
            #pragma unroll
            for (int r = 0; r < 4; r++) {
                u2[r][q][0] = relu2(u2[r][q][0]);
                u2[r][q][1] = relu2(u2[r][q][1]);
            }

        // ---- layer-2 local partials into slot array v[32]; slot i = r*8+j ----
        float v[32];
        #pragma unroll
        for (int j = 0; j < 6; j++) {
            ulonglong2 w0 = *(const ulonglong2*)(wd2w + j * 256);
            ulonglong2 w1 = *(const ulonglong2*)(wd2w + j * 256 + 128);
            #pragma unroll
            for (int r = 0; r < 4; r++) {
                u64 a2 = ffma2(u2[r][2][0], w0.x, 0ULL);
                a2 = ffma2(u2[r][2][1], w0.y, a2);
                a2 = ffma2(u2[r][3][0], w1.x, a2);
                a2 = ffma2(u2[r][3][1], w1.y, a2);
                float2 q = unpk(a2);
                v[r * 8 + j] = q.x + q.y;
            }
        }
        {
            ulonglong2 w0 = *(const ulonglong2*)(wen2w);
            ulonglong2 w1 = *(const ulonglong2*)(wen2w + 128);
            #pragma unroll
            for (int r = 0; r < 4; r++) {
                u64 s2 = ffma2(u2[r][0][0], w0.x, 0ULL);
                s2 = ffma2(u2[r][0][1], w0.y, s2);
                s2 = ffma2(u2[r][1][0], w1.x, s2);
                s2 = ffma2(u2[r][1][1], w1.y, s2);
                float2 q = unpk(s2);
                v[r * 8 + 6] = q.x + q.y;
                v[r * 8 + 7] = 0.f;
            }
        }

        // ---- fold-distribute reduction: lane i ends with sum over lanes of v[i] ----
        #pragma unroll
        for (int lvl = 0; lvl < 5; lvl++) {
            const int off = 16 >> lvl;
            #pragma unroll
            for (int m = 0; m < (16 >> lvl); m++) {
                float send = (lane & off) ? v[m] : v[m + off];
                float recv = __shfl_xor_sync(0xffffffffu, send, off);
                float keep = (lane & off) ? v[m + off] : v[m];
                v[m] = keep + recv;
            }
        }

        // ---- outputs: xi BEFORE update (owners j<6), stress (j==6) ----
        if (jown < 6)       xi_ptr[t * 6] = xi_val;
        else if (jown == 6) s_ptr[t] = v[0] + ben2r;

        // explicit Euler update (garbage on non-owner lanes, never read)
        xi_val = fmaf(DT_, v[0] + bd2v, xi_val);

        // ---- front half for t+1: independent of xi_val; covers the fold/output tail ----
        FRONT(nxt0, nxt1)
    }
    #undef FRONT
}

extern "C" void kernel_launch(void* const* d_in, const int* in_sizes, int n_in,
                              void* d_out, int out_size) {
    (void)in_sizes; (void)n_in; (void)out_size;
    cudaFuncSetAttribute(visco_kernel,
                         cudaFuncAttributeMaxDynamicSharedMemorySize, SMEM_BYTES);
    visco_kernel<<<NBLK, THREADS, SMEM_BYTES>>>(
        (const float*)d_in[0],  (const float*)d_in[1],
        (const float*)d_in[2],  (const float*)d_in[3],
        (const float*)d_in[4],  (const float*)d_in[5],
        (const float*)d_in[6],  (const float*)d_in[7],
        (const float*)d_in[8],  (const float*)d_in[9],
        (const float*)d_in[10], (const float*)d_in[11],
        (const float*)d_in[12], (const float*)d_in[13],
        (const float*)d_in[14], (const float*)d_in[15],
        (float*)d_out);
}

// round 16
// speedup vs baseline: 3.3958x; 3.3958x over previous
#include <cuda_runtime.h>

#define B_ 8192
#define T_ 128
#define DT_ 0.01f
#define WARPS 4
#define THREADS 128
#define ROWS_PER_BLOCK 16
#define NBLK (B_ / ROWS_PER_BLOCK)

// shared memory layout (float offsets)
// W1s rows: 0..17 dynamic (e6, ed6, xi6); 18 = beta (xE); 19 = gamma (xnu); 20 = alpha
#define OFF_W1   0        // [21][512]
#define OFF_WEN2 10752    // [256]
#define OFF_WD2T 11008    // [6][256] (transposed Wd2)
#define SMEM_FLOATS 12544
#define SMEM_BYTES (SMEM_FLOATS * 4)

typedef unsigned long long u64;

__device__ __forceinline__ u64 ffma2(u64 a, u64 b, u64 c) {
    u64 d; asm("fma.rn.f32x2 %0, %1, %2, %3;" : "=l"(d) : "l"(a), "l"(b), "l"(c));
    return d;
}
__device__ __forceinline__ u64 dup2(float x) {
    u64 d; asm("mov.b64 %0, {%1, %1};" : "=l"(d) : "f"(x));
    return d;
}
__device__ __forceinline__ float2 unpk(u64 a) {
    float2 r; asm("mov.b64 {%0, %1}, %2;" : "=f"(r.x), "=f"(r.y) : "l"(a));
    return r;
}
__device__ __forceinline__ u64 pk2(float x, float y) {
    u64 d; asm("mov.b64 %0, {%1, %2};" : "=l"(d) : "f"(x), "f"(y));
    return d;
}
__device__ __forceinline__ u64 relu2(u64 a) {
    float2 v = unpk(a);
    return pk2(fmaxf(v.x, 0.f), fmaxf(v.y, 0.f));
}

__global__ void __launch_bounds__(THREADS, 3) visco_kernel(
    const float* __restrict__ e_,   const float* __restrict__ ed_,
    const float* __restrict__ E_,   const float* __restrict__ nu_,
    const float* __restrict__ We,   const float* __restrict__ be,
    const float* __restrict__ Wn,   const float* __restrict__ bn,
    const float* __restrict__ Wen1, const float* __restrict__ ben1,
    const float* __restrict__ Wen2, const float* __restrict__ ben2,
    const float* __restrict__ Wd1,  const float* __restrict__ bd1,
    const float* __restrict__ Wd2,  const float* __restrict__ bd2,
    float* __restrict__ out)
{
    extern __shared__ float sm[];
    float* W1s   = sm + OFF_W1;
    float* Wen2s = sm + OFF_WEN2;
    float* Wd2t  = sm + OFF_WD2T;

    const int tid  = threadIdx.x;
    const int lane = tid & 31;
    const int warp = tid >> 5;

    // ---- cooperative smem fill: dynamic W1 rows 0..17 + layer-2 weights ----
    for (int i = tid; i < 18 * 512; i += THREADS) {
        int k = i >> 9, h = i & 511;
        W1s[i] = (h < 256) ? Wen1[k * 256 + h] : Wd1[k * 256 + (h - 256)];
    }
    for (int i = tid; i < 256; i += THREADS) Wen2s[i] = Wen2[i];
    for (int i = tid; i < 6 * 256; i += THREADS) {
        int j = i >> 8, h = i & 255;
        Wd2t[i] = Wd2[h * 6 + j];   // transpose -> conflict-free float4 reads
    }

    // ---- rows 18..20: beta = We@W1mf, gamma = Wn@W1mf, alpha = bias fold ----
    // mf = [E*We+be, nu*Wn+bn]  =>  c[h] = alpha[h] + E*beta[h] + nu*gamma[h]
    {
        const int h0 = 4 * tid;
        const float* bsrc = (h0 < 256) ? (ben1 + h0) : (bd1 + h0 - 256);
        const float* Wb   = (h0 < 256) ? (Wen1 + 18 * 256 + h0)
                                       : (Wd1  + 18 * 256 + h0 - 256);
        float al[4], bt[4], gm[4];
        #pragma unroll
        for (int el = 0; el < 4; el++) { al[el] = bsrc[el]; bt[el] = 0.f; gm[el] = 0.f; }
        for (int i = 0; i < 16; i++) {
            float4 wa = *(const float4*)(Wb + i * 256);          // W1 row 18+i (E-encoder)
            float4 wb = *(const float4*)(Wb + (16 + i) * 256);   // W1 row 34+i (nu-encoder)
            float wev = We[i], bev = be[i], wnv = Wn[i], bnv = bn[i];
            bt[0] = fmaf(wev, wa.x, bt[0]); bt[1] = fmaf(wev, wa.y, bt[1]);
            bt[2] = fmaf(wev, wa.z, bt[2]); bt[3] = fmaf(wev, wa.w, bt[3]);
            gm[0] = fmaf(wnv, wb.x, gm[0]); gm[1] = fmaf(wnv, wb.y, gm[1]);
            gm[2] = fmaf(wnv, wb.z, gm[2]); gm[3] = fmaf(wnv, wb.w, gm[3]);
            al[0] = fmaf(bev, wa.x, al[0]); al[1] = fmaf(bev, wa.y, al[1]);
            al[2] = fmaf(bev, wa.z, al[2]); al[3] = fmaf(bev, wa.w, al[3]);
            al[0] = fmaf(bnv, wb.x, al[0]); al[1] = fmaf(bnv, wb.y, al[1]);
            al[2] = fmaf(bnv, wb.z, al[2]); al[3] = fmaf(bnv, wb.w, al[3]);
        }
        *(float4*)(W1s + 18 * 512 + h0) = make_float4(bt[0], bt[1], bt[2], bt[3]);
        *(float4*)(W1s + 19 * 512 + h0) = make_float4(gm[0], gm[1], gm[2], gm[3]);
        *(float4*)(W1s + 20 * 512 + h0) = make_float4(al[0], al[1], al[2], al[3]);
    }

    const int gw   = blockIdx.x * WARPS + warp;
    const int row0 = gw * 4;

    // per-row E/nu kept in registers as pre-duplicated f32x2 (as in champion R10)
    u64 Ed[4], nud[4];
    #pragma unroll
    for (int r = 0; r < 4; r++) {
        Ed[r]  = dup2(E_[row0 + r]);
        nud[r] = dup2(nu_[row0 + r]);
    }

    // ---- distributed state: lane i = r*8+j owns output slot (r, j) ----
    const int jown = lane & 7;
    const int rown = lane >> 3;
    const float bd2v  = (jown < 6) ? bd2[jown] : 0.f;
    const float ben2r = ben2[0];
    float xi_val = 0.f;

    float* xi_ptr = out + B_ * T_ + ((row0 + rown) * T_) * 6 + jown;   // += 6 per step
    float* s_ptr  = out + (row0 + rown) * T_;                          // += 1 per step

    // lane -> (rowpair, input-dim) mapping for the per-step e/edot gather
    const int l2  = lane & 15;
    const bool ldp = (l2 < 12);
    const float* lsrc = (l2 < 6) ? e_ : ed_;
    const int d_l = (l2 < 6) ? l2 : (l2 - 6);
    const int rA = row0 + ((lane < 16) ? 0 : 1);
    const int rB = row0 + ((lane < 16) ? 2 : 3);
    const int base0 = rA * T_ * 6 + d_l;
    const int base1 = rB * T_ * 6 + d_l;

    const float* W1w   = W1s + 4 * lane;            // + k*512 + 128*q
    const float* wen2w = Wen2s + 4 * lane;          // + 128*q
    const float* wd2w  = Wd2t + 4 * lane;           // + j*256 + 128*q

    __syncthreads();

    float nxt0 = 0.f, nxt1 = 0.f;
    if (ldp) { nxt0 = lsrc[base0]; nxt1 = lsrc[base1]; }

    for (int t = 0; t < T_; t++) {
        const float ld0 = nxt0, ld1 = nxt1;
        {
            int tn = (t + 1 < T_) ? (t + 1) : (T_ - 1);
            if (ldp) { nxt0 = lsrc[base0 + tn * 6]; nxt1 = lsrc[base1 + tn * 6]; }
        }

        // ---- fused init: u2 = alpha + nu*gamma + E*beta (replaces MOV-init + k=18,19) ----
        u64 u2[4][4][2];   // [row][q][pair] — strictly loop-local (no cross-edge lifetime)
        #pragma unroll
        for (int q = 0; q < 4; q++) {
            ulonglong2 a  = *(const ulonglong2*)(W1w + 20 * 512 + 128 * q);
            ulonglong2 wg = *(const ulonglong2*)(W1w + 19 * 512 + 128 * q);
            ulonglong2 wb = *(const ulonglong2*)(W1w + 18 * 512 + 128 * q);
            #pragma unroll
            for (int r = 0; r < 4; r++) {
                u2[r][q][0] = ffma2(Ed[r], wb.x, ffma2(nud[r], wg.x, a.x));
                u2[r][q][1] = ffma2(Ed[r], wb.y, ffma2(nud[r], wg.y, a.y));
            }
        }

        // ---- layer 1: 18 dynamic inputs x 512 hidden (W1 LDS shared by 4 rows) ----
        #pragma unroll
        for (int k = 0; k < 18; k++) {
            u64 xd[4];
            if (k < 12) {
                xd[0] = dup2(__shfl_sync(0xffffffffu, ld0, k));
                xd[1] = dup2(__shfl_sync(0xffffffffu, ld0, 16 + k));
                xd[2] = dup2(__shfl_sync(0xffffffffu, ld1, k));
                xd[3] = dup2(__shfl_sync(0xffffffffu, ld1, 16 + k));
            } else {
                // xi[r][k-12] lives in lane r*8 + (k-12)
                const int js = k - 12;
                xd[0] = dup2(__shfl_sync(0xffffffffu, xi_val, 0 * 8 + js));
                xd[1] = dup2(__shfl_sync(0xffffffffu, xi_val, 1 * 8 + js));
                xd[2] = dup2(__shfl_sync(0xffffffffu, xi_val, 2 * 8 + js));
                xd[3] = dup2(__shfl_sync(0xffffffffu, xi_val, 3 * 8 + js));
            }
            #pragma unroll
            for (int q = 0; q < 4; q++) {
                ulonglong2 w = *(const ulonglong2*)(W1w + k * 512 + 128 * q);
                #pragma unroll
                for (int r = 0; r < 4; r++) {
                    u2[r][q][0] = ffma2(xd[r], w.x, u2[r][q][0]);
                    u2[r][q][1] = ffma2(xd[r], w.y, u2[r][q][1]);
                }
            }
        }

        // relu
        #pragma unroll
        for (int q = 0; q < 4; q++)
            #pragma unroll
            for (int r = 0; r < 4; r++) {
                u2[r][q][0] = relu2(u2[r][q][0]);
                u2[r][q][1] = relu2(u2[r][q][1]);
            }

        // ---- layer-2 local partials into slot array v[32]; slot i = r*8+j ----
        float v[32];
        // kinetics (q=2,3): j outer so weight loads stay transient
        #pragma unroll
        for (int j = 0; j < 6; j++) {
            ulonglong2 w0 = *(const ulonglong2*)(wd2w + j * 256);
            ulonglong2 w1 = *(const ulonglong2*)(wd2w + j * 256 + 128);
            #pragma unroll
            for (int r = 0; r < 4; r++) {
                u64 a2 = ffma2(u2[r][2][0], w0.x, 0ULL);
                a2 = ffma2(u2[r][2][1], w0.y, a2);
                a2 = ffma2(u2[r][3][0], w1.x, a2);
                a2 = ffma2(u2[r][3][1], w1.y, a2);
                float2 q = unpk(a2);
                v[r * 8 + j] = q.x + q.y;
            }
        }
        // stress (q=0,1)
        {
            ulonglong2 w0 = *(const ulonglong2*)(wen2w);
            ulonglong2 w1 = *(const ulonglong2*)(wen2w + 128);
            #pragma unroll
            for (int r = 0; r < 4; r++) {
                u64 s2 = ffma2(u2[r][0][0], w0.x, 0ULL);
                s2 = ffma2(u2[r][0][1], w0.y, s2);
                s2 = ffma2(u2[r][1][0], w1.x, s2);
                s2 = ffma2(u2[r][1][1], w1.y, s2);
                float2 q = unpk(s2);
                v[r * 8 + 6] = q.x + q.y;
                v[r * 8 + 7] = 0.f;
            }
        }

        // ---- fold-distribute reduction: lane i ends with sum over lanes of v[i] ----
        #pragma unroll
        for (int lvl = 0; lvl < 5; lvl++) {
            const int off = 16 >> lvl;
            #pragma unroll
            for (int m = 0; m < (16 >> lvl); m++) {
                float send = (lane & off) ? v[m] : v[m + off];
                float recv = __shfl_xor_sync(0xffffffffu, send, off);
                float keep = (lane & off) ? v[m + off] : v[m];
                v[m] = keep + recv;
            }
        }
        // v[0] now holds this lane's owned slot value

        // ---- outputs: xi BEFORE update (owner lanes j<6), stress (j==6) ----
        if (jown < 6)       *xi_ptr = xi_val;
        else if (jown == 6) *s_ptr = v[0] + ben2r;
        xi_ptr += 6;
        s_ptr  += 1;

        // explicit Euler update (garbage on non-owner lanes, never read)
        xi_val = fmaf(DT_, v[0] + bd2v, xi_val);
    }
}

extern "C" void kernel_launch(void* const* d_in, const int* in_sizes, int n_in,
                              void* d_out, int out_size) {
    (void)in_sizes; (void)n_in; (void)out_size;
    cudaFuncSetAttribute(visco_kernel,
                         cudaFuncAttributeMaxDynamicSharedMemorySize, SMEM_BYTES);
    visco_kernel<<<NBLK, THREADS, SMEM_BYTES>>>(
        (const float*)d_in[0],  (const float*)d_in[1],
        (const float*)d_in[2],  (const float*)d_in[3],
        (const float*)d_in[4],  (const float*)d_in[5],
        (const float*)d_in[6],  (const float*)d_in[7],
        (const float*)d_in[8],  (const float*)d_in[9],
        (const float*)d_in[10], (const float*)d_in[11],
        (const float*)d_in[12], (const float*)d_in[13],
        (const float*)d_in[14], (const float*)d_in[15],
        (float*)d_out);
}